// round 11
// baseline (speedup 1.0000x reference)
#include <cuda_runtime.h>
#include <cstdint>

#define T_STEPS 512
#define BATCH   2048
#define F_IN    64
#define HID     32
#define NGATE   128   // 4*HID
#define PFD     3     // recur prefetch distance (steps)

typedef unsigned long long ull;

// x_proj scratch, CELL-MAJOR gate quads: entry [t][b][cell*4 + gtype].
// Padded by 4 steps so recur's distance-PFD prefetch never reads OOB.
__device__ float g_xproj[(size_t)(T_STEPS + 4) * BATCH * NGATE];

__device__ __forceinline__ ull pack2(float lo, float hi) {
    ull r;
    asm("mov.b64 %0, {%1,%2};" : "=l"(r) : "f"(lo), "f"(hi));
    return r;
}
__device__ __forceinline__ void unpack2(ull p, float &lo, float &hi) {
    asm("mov.b64 {%0,%1}, %2;" : "=f"(lo), "=f"(hi) : "l"(p));
}
// packed f32x2 fma: d = a*b + c (lane-wise)
__device__ __forceinline__ ull fma2(ull a, ull b, ull c) {
    ull d;
    asm("fma.rn.f32x2 %0, %1, %2, %3;" : "=l"(d) : "l"(a), "l"(b), "l"(c));
    return d;
}
__device__ __forceinline__ float tanh_fast(float x) {
    float y;
    asm("tanh.approx.f32 %0, %1;" : "=f"(y) : "f"(x));
    return y;
}
__device__ __forceinline__ float sigm_fast(float x) {
    return fmaf(0.5f, tanh_fast(0.5f * x), 0.5f);
}
__device__ __forceinline__ void cp16(void* smem, const void* gmem) {
    uint32_t s = (uint32_t)__cvta_generic_to_shared(smem);
    asm volatile("cp.async.cg.shared.global [%0], [%1], 16;" :: "r"(s), "l"(gmem));
}

// ============================================================================
// Kernel A: x_proj = x @ W_ih^T + (b_ih + b_hh)   -- [1M, 64] x [64, 128]
// PERSISTENT version: 2048 CTAs x 8 tiles (64 samples each). W staged once
// per CTA; x tiles double-buffered via cp.async so staging hides under the
// previous tile's FMA block. k lives in f32x2 lanes (raw-byte staging).
// ============================================================================
#define XS     64     // samples per tile
#define WPIT   34     // ull pitch (32 data + 2 pad)
#define NT     8      // tiles per CTA
#define W_ULL  (NGATE * WPIT)            // 4352 ull = 34816 B
#define XB_ULL (XS * WPIT)               // 2176 ull = 17408 B
#define SMEM_X ((W_ULL + 2 * XB_ULL) * 8)  // 69632 B (dynamic)

__global__ void __launch_bounds__(256, 2)
xproj_kernel(const float* __restrict__ x,
             const float* __restrict__ W_ih,
             const float* __restrict__ b_ih,
             const float* __restrict__ b_hh)
{
    extern __shared__ __align__(16) ull sm[];
    ull* wrow = sm;                       // [NGATE][WPIT]
    ull* xbuf[2] = { sm + W_ULL, sm + W_ULL + XB_ULL };   // [XS][WPIT] each

    const int t  = threadIdx.x;
    const int tx = t & 15;               // gates: tx + 16p, p=0..7
    const int ty = t >> 4;               // samples: ty*4 .. ty*4+3

    // ---- stage W once (32 KB), coalesced; raw bytes == k-pair ull layout ----
    {
        const float4* wg = reinterpret_cast<const float4*>(W_ih);
#pragma unroll
        for (int i = 0; i < 8; i++) {
            const int idx = t + 256 * i;      // float4 index, g-major
            const int g = idx >> 4;
            const int c = idx & 15;
            const float4 v = wg[idx];
            *reinterpret_cast<float4*>(&wrow[g * WPIT + 2 * c]) = v;
        }
    }
    // bias (lo-lane init trick: acc = {bias + even-k sum, odd-k sum})
    float bf[8];
#pragma unroll
    for (int p = 0; p < 8; p++) {
        const int g = tx + 16 * p;
        bf[p] = b_ih[g] + b_hh[g];
    }

    const int tile0 = blockIdx.x * NT;

    // ---- stage helper: 4 cp.async(16B) per thread, coalesced ----
    auto stage = [&](int buf, int tile) {
        const float* src = x + (size_t)tile * XS * F_IN;
#pragma unroll
        for (int i = 0; i < 4; i++) {
            const int idx = t + 256 * i;          // float4 id in tile
            const int s = idx >> 4;
            const int c = idx & 15;
            cp16(&xbuf[buf][s * WPIT + 2 * c], src + idx * 4);
        }
    };

    stage(0, tile0);
    asm volatile("cp.async.commit_group;");

#pragma unroll 1
    for (int it = 0; it < NT; it++) {
        if (it + 1 < NT) {
            stage((it + 1) & 1, tile0 + it + 1);
            asm volatile("cp.async.commit_group;");
            asm volatile("cp.async.wait_group 1;");   // tile 'it' complete
        } else {
            asm volatile("cp.async.wait_group 0;");
        }
        __syncthreads();

        const ull* xr = xbuf[it & 1];

        // acc init: bias in lo lane
        ull acc[4][8];
#pragma unroll
        for (int p = 0; p < 8; p++) {
            const ull b = pack2(bf[p], 0.0f);
#pragma unroll
            for (int q = 0; q < 4; q++) acc[q][p] = b;
        }

        // main loop: per 2 kk: 12 LDS.128 feed 64 FFMA2
#pragma unroll 4
        for (int kk = 0; kk < 32; kk += 2) {
            ulonglong2 xq[4], wq[8];
#pragma unroll
            for (int q = 0; q < 4; q++)
                xq[q] = *reinterpret_cast<const ulonglong2*>(
                    &xr[(ty * 4 + q) * WPIT + kk]);
#pragma unroll
            for (int p = 0; p < 8; p++)
                wq[p] = *reinterpret_cast<const ulonglong2*>(
                    &wrow[(tx + 16 * p) * WPIT + kk]);
#pragma unroll
            for (int q = 0; q < 4; q++)
#pragma unroll
                for (int p = 0; p < 8; p++) {
                    acc[q][p] = fma2(xq[q].x, wq[p].x, acc[q][p]);
                    acc[q][p] = fma2(xq[q].y, wq[p].y, acc[q][p]);
                }
        }

        // writeout: cell-major gate quads, coalesced STG.128
        const size_t row0 = (size_t)(tile0 + it) * XS;
#pragma unroll
        for (int q = 0; q < 4; q++) {
            float hlo, hhi;
            float4 v0, v1;
            unpack2(acc[q][0], hlo, hhi); v0.x = hlo + hhi;   // i, cell tx
            unpack2(acc[q][2], hlo, hhi); v0.y = hlo + hhi;   // f
            unpack2(acc[q][4], hlo, hhi); v0.z = hlo + hhi;   // g
            unpack2(acc[q][6], hlo, hhi); v0.w = hlo + hhi;   // o
            unpack2(acc[q][1], hlo, hhi); v1.x = hlo + hhi;   // cell tx+16
            unpack2(acc[q][3], hlo, hhi); v1.y = hlo + hhi;
            unpack2(acc[q][5], hlo, hhi); v1.z = hlo + hhi;
            unpack2(acc[q][7], hlo, hhi); v1.w = hlo + hhi;
            float4* op4 = reinterpret_cast<float4*>(
                g_xproj + (row0 + ty * 4 + q) * NGATE);
            op4[tx]      = v0;
            op4[tx + 16] = v1;
        }
        __syncthreads();   // all reads of xbuf[it&1] done before re-staging
    }
}

// ============================================================================
// Kernel B: recurrence (round-9, unchanged). Single-warp CTA, 2 samples;
// cp.async 4-slot ring streams x_proj with a true 3-step shadow.
// ============================================================================
__global__ void __launch_bounds__(32)
recur_kernel(const float* __restrict__ W_hh,
             const float* __restrict__ W_d,
             const float* __restrict__ b_d,
             float* __restrict__ out)
{
    __shared__ __align__(16) float4 xring[4][2][32];   // [slot][sample][lane] 4 KB
    __shared__ ull hp[2][2][HID / 2];                  // [buf][sample][kpair] 512 B

    const int t  = threadIdx.x;         // lane = cell index
    const int bA = blockIdx.x * 2;      // samples bA, bA+1

    // weight rows t, t+32, t+64, t+96 packed along k (shared by both samples)
    ull wI[16], wF[16], wG[16], wO[16];
    {
        const ull* wr = reinterpret_cast<const ull*>(W_hh);
#pragma unroll
        for (int kk = 0; kk < 16; kk++) {
            wI[kk] = wr[(t)      * 16 + kk];
            wF[kk] = wr[(t + 32) * 16 + kk];
            wG[kk] = wr[(t + 64) * 16 + kk];
            wO[kk] = wr[(t + 96) * 16 + kk];
        }
    }

    if (t < HID / 2) { hp[0][0][t] = 0ULL; hp[0][1][t] = 0ULL; }
    float cA = 0.0f, cB = 0.0f;

    const float4* gxA = reinterpret_cast<const float4*>(
        g_xproj + (size_t)bA * NGATE) + t;
    const float4* gxB = gxA + NGATE / 4;
    const size_t s4 = (size_t)BATCH * NGATE / 4;   // float4 step stride

    // prologue: slots 0..2 <- steps 0..2, one group per step
#pragma unroll
    for (int i = 0; i < PFD; i++) {
        cp16(&xring[i][0][t], gxA + (size_t)i * s4);
        cp16(&xring[i][1][t], gxB + (size_t)i * s4);
        asm volatile("cp.async.commit_group;");
    }
    __syncwarp();

#pragma unroll 1
    for (int ts0 = 0; ts0 < T_STEPS; ts0 += 4) {
#pragma unroll
        for (int u = 0; u < 4; u++) {
            const int ts = ts0 + u;
            const int slot = (ts + PFD) & 3;
            cp16(&xring[slot][0][t], gxA + (size_t)(ts + PFD) * s4);
            cp16(&xring[slot][1][t], gxB + (size_t)(ts + PFD) * s4);
            asm volatile("cp.async.commit_group;");
            asm volatile("cp.async.wait_group 3;");

            const float4 curA = xring[ts & 3][0][t];
            const float4 curB = xring[ts & 3][1][t];
            const int rb = ts & 1;
            const ulonglong2* hqA = reinterpret_cast<const ulonglong2*>(hp[rb][0]);
            const ulonglong2* hqB = reinterpret_cast<const ulonglong2*>(hp[rb][1]);

            // phase 1: 4 gate rows x 2 samples, h broadcast from smem
            ull aIA = pack2(curA.x, 0.0f), aFA = pack2(curA.y, 0.0f);
            ull aGA = pack2(curA.z, 0.0f), aOA = pack2(curA.w, 0.0f);
            ull aIB = pack2(curB.x, 0.0f), aFB = pack2(curB.y, 0.0f);
            ull aGB = pack2(curB.z, 0.0f), aOB = pack2(curB.w, 0.0f);
#pragma unroll
            for (int k2 = 0; k2 < 8; k2++) {
                const ulonglong2 hvA = hqA[k2];
                const ulonglong2 hvB = hqB[k2];
                aIA = fma2(hvA.x, wI[2 * k2], aIA);
                aIB = fma2(hvB.x, wI[2 * k2], aIB);
                aFA = fma2(hvA.x, wF[2 * k2], aFA);
                aFB = fma2(hvB.x, wF[2 * k2], aFB);
                aGA = fma2(hvA.x, wG[2 * k2], aGA);
                aGB = fma2(hvB.x, wG[2 * k2], aGB);
                aOA = fma2(hvA.x, wO[2 * k2], aOA);
                aOB = fma2(hvB.x, wO[2 * k2], aOB);
                aIA = fma2(hvA.y, wI[2 * k2 + 1], aIA);
                aIB = fma2(hvB.y, wI[2 * k2 + 1], aIB);
                aFA = fma2(hvA.y, wF[2 * k2 + 1], aFA);
                aFB = fma2(hvB.y, wF[2 * k2 + 1], aFB);
                aGA = fma2(hvA.y, wG[2 * k2 + 1], aGA);
                aGB = fma2(hvB.y, wG[2 * k2 + 1], aGB);
                aOA = fma2(hvA.y, wO[2 * k2 + 1], aOA);
                aOB = fma2(hvB.y, wO[2 * k2 + 1], aOB);
            }
            float lo, hi;
            unpack2(aIA, lo, hi); const float igA = sigm_fast(lo + hi);
            unpack2(aIB, lo, hi); const float igB = sigm_fast(lo + hi);
            unpack2(aFA, lo, hi); const float fgA = sigm_fast(lo + hi);
            unpack2(aFB, lo, hi); const float fgB = sigm_fast(lo + hi);
            unpack2(aGA, lo, hi); const float ggA = tanh_fast(lo + hi);
            unpack2(aGB, lo, hi); const float ggB = tanh_fast(lo + hi);
            unpack2(aOA, lo, hi); const float ogA = sigm_fast(lo + hi);
            unpack2(aOB, lo, hi); const float ogB = sigm_fast(lo + hi);

            // phase 2: thread-local cell updates, write to OTHER buffer
            cA = fgA * cA + igA * ggA;
            cB = fgB * cB + igB * ggB;
            const float hA = ogA * tanh_fast(cA);
            const float hB = ogB * tanh_fast(cB);
            reinterpret_cast<float*>(hp[1 - rb][0])[t] = hA;
            reinterpret_cast<float*>(hp[1 - rb][1])[t] = hB;

            __syncwarp();   // h buffer (1-rb) visible for next step
        }
    }

    // epilogue: out[b, a] = relu(h_T) @ W_d^T + b_d
    if ((t & 3) < 3 && t < 8) {
        const int s = t >> 2;       // 0 = sample A, 1 = sample B
        const int a = t & 3;        // action
        float sum = b_d[a];
        const float* hf = reinterpret_cast<const float*>(hp[T_STEPS & 1][s]);
#pragma unroll
        for (int j = 0; j < HID; j++)
            sum += fmaxf(hf[j], 0.0f) * W_d[a * HID + j];
        out[(size_t)(bA + s) * 3 + a] = sum;
    }
}

extern "C" void kernel_launch(void* const* d_in, const int* in_sizes, int n_in,
                              void* d_out, int out_size)
{
    const float* x    = (const float*)d_in[0];
    const float* W_ih = (const float*)d_in[1];
    const float* W_hh = (const float*)d_in[2];
    const float* b_ih = (const float*)d_in[3];
    const float* b_hh = (const float*)d_in[4];
    const float* W_d  = (const float*)d_in[5];
    const float* b_d  = (const float*)d_in[6];
    float* out = (float*)d_out;

    static bool smem_set = false;
    cudaFuncSetAttribute(xproj_kernel,
                         cudaFuncAttributeMaxDynamicSharedMemorySize, SMEM_X);
    (void)smem_set;

    // Kernel A: persistent x_proj GEMM (2048 CTAs x 8 tiles)
    {
        dim3 grid((T_STEPS * BATCH) / (XS * NT));   // 2048 CTAs
        dim3 block(256);
        xproj_kernel<<<grid, block, SMEM_X>>>(x, W_ih, b_ih, b_hh);
    }
    // Kernel B: sequential LSTM recurrence + decode head
    {
        dim3 grid(BATCH / 2);                        // 1024 single-warp CTAs
        dim3 block(32);
        recur_kernel<<<grid, block>>>(W_hh, W_d, b_d, out);
    }
}